// round 11
// baseline (speedup 1.0000x reference)
#include <cuda_runtime.h>
#include <cuda_bf16.h>
#include <cstdint>
#include <math.h>

#define BATCH 256
#define SEQ 256
#define IN_DIM 128
#define HID 1024
#define OUT_DIM 10
#define KTOT 1152            // [h | x_t] fused K
#define BK 32
#define BM 32
#define BN 64
#define LDW 40               // bf16 elems per row slot (80B) -> conflict-free ldmatrix
#define NT 256               // 8 warps = 2/SMSP

// stage layout (bytes): Ah[32][40] Al[32][40] Bh[64][40] Bl[64][40]  (bf16)
#define OFF_AL 2560
#define OFF_BH 5120
#define OFF_BL 10240
#define STAGE_B 15360
#define NSTAGE 3
#define DYN_B (NSTAGE * STAGE_B)   // 46080

// ---- device-global scratch (sanctioned) ----
__device__ __nv_bfloat16 g_hh[2][BATCH * HID];   // hidden hi split (ping-pong)
__device__ __nv_bfloat16 g_hl[2][BATCH * HID];   // hidden lo split
__device__ __nv_bfloat16 g_xh[BATCH * SEQ * IN_DIM];
__device__ __nv_bfloat16 g_xl[BATCH * SEQ * IN_DIM];
__device__ __nv_bfloat16 g_Wh[HID * KTOT];       // W^T [n][k] hi
__device__ __nv_bfloat16 g_Wl[HID * KTOT];       // lo

__device__ __forceinline__ void cp16(void* smem_dst, const void* g) {
    unsigned d = (unsigned)__cvta_generic_to_shared(smem_dst);
    asm volatile("cp.async.ca.shared.global [%0], [%1], 16;\n" :: "r"(d), "l"(g));
}
__device__ __forceinline__ void cp_commit() { asm volatile("cp.async.commit_group;\n"); }
template <int N>
__device__ __forceinline__ void cp_wait() { asm volatile("cp.async.wait_group %0;\n" :: "n"(N)); }

__device__ __forceinline__ void ldsm4(unsigned* r, unsigned saddr) {
    asm volatile("ldmatrix.sync.aligned.m8n8.x4.shared.b16 {%0,%1,%2,%3}, [%4];"
                 : "=r"(r[0]), "=r"(r[1]), "=r"(r[2]), "=r"(r[3]) : "r"(saddr));
}
__device__ __forceinline__ void mma_bf16(float* c, const unsigned* a, unsigned b0, unsigned b1) {
    asm volatile(
        "mma.sync.aligned.m16n8k16.row.col.f32.bf16.bf16.f32 "
        "{%0,%1,%2,%3}, {%4,%5,%6,%7}, {%8,%9}, {%0,%1,%2,%3};"
        : "+f"(c[0]), "+f"(c[1]), "+f"(c[2]), "+f"(c[3])
        : "r"(a[0]), "r"(a[1]), "r"(a[2]), "r"(a[3]), "r"(b0), "r"(b1));
}

// ---- prep: transpose + bf16 hi/lo split of W; split x ----
__global__ void split_w(const float* __restrict__ Whh, const float* __restrict__ Whx) {
    int k = blockIdx.x;                          // 0..1151
    for (int n = threadIdx.x; n < HID; n += blockDim.x) {
        float w = (k < HID) ? Whh[(long)k * HID + n] : Whx[(long)(k - HID) * HID + n];
        __nv_bfloat16 hi = __float2bfloat16(w);
        g_Wh[(long)n * KTOT + k] = hi;
        g_Wl[(long)n * KTOT + k] = __float2bfloat16(w - __bfloat162float(hi));
    }
}
__global__ void split_x(const float* __restrict__ x) {
    long i = (long)blockIdx.x * blockDim.x + threadIdx.x;
    if (i < (long)BATCH * SEQ * IN_DIM) {
        float v = x[i];
        __nv_bfloat16 hi = __float2bfloat16(v);
        g_xh[i] = hi;
        g_xl[i] = __float2bfloat16(v - __bfloat162float(hi));
    }
}

// ---- one recurrence step: 3-term bf16x2 split via mma.sync m16n8k16 ----
// grid (16, 8) = 128 CTAs, 256 threads (8 warps), warp tile 16x16 (2m x 4n).
__global__ __launch_bounds__(NT, 1) void rnn_step(
    const float* __restrict__ bh, int t)
{
    extern __shared__ char smem[];

    const int tid  = threadIdx.x;
    const int wid  = tid >> 5;
    const int lane = tid & 31;
    const int g    = lane >> 2;     // fragment group 0..7
    const int tg   = lane & 3;      // thread-in-group 0..3
    const int wm   = wid & 1;       // warp m 0..1 (16 rows)
    const int wn   = wid >> 1;      // warp n 0..3 (16 cols)

    const int bm = blockIdx.y * BM;
    const int bn = blockIdx.x * BN;

    const unsigned sbase = (unsigned)__cvta_generic_to_shared(smem);

    // ldmatrix per-lane source offsets (bytes within a stage), b16 flavor.
    // A x4 -> a0..a3 of m16n8k16 (mats: m0-7/k0-7, m8-15/k0-7, m0-7/k8-15, m8-15/k8-15)
    const int a_row = wm * 16 + (lane & 15);
    const unsigned aoff = (unsigned)(a_row * LDW + ((lane >> 4) << 3)) * 2u;
    // B x4 -> b0,b1 (n-group 0), b0,b1 (n-group 1)
    const int b_row = wn * 16 + (lane & 7) + ((lane >> 4) << 3);
    const unsigned boff = (unsigned)(b_row * LDW + (((lane >> 3) & 1) << 3)) * 2u;

    const __nv_bfloat16* hh_in = g_hh[t & 1];
    const __nv_bfloat16* hl_in = g_hl[t & 1];
    __nv_bfloat16* hh_out = g_hh[(t & 1) ^ 1];
    __nv_bfloat16* hl_out = g_hl[(t & 1) ^ 1];

    const int kstart = (t == 0) ? HID : 0;      // t==0: h0==0, only x chunks
    const int NC = (KTOT - kstart) / BK;        // 36 (or 4 at t==0)

    auto load_chunk = [&](int ci, int s) {
        const int k0 = kstart + ci * BK;
        char* st = smem + s * STAGE_B;
        const bool isH = (k0 < HID);
        {   // A: 2 splits x 32 rows x 4 kq of 8 bf16 = 256 cp16, 1/thread
            int hi  = (tid < 128);
            int row = tid & 31;
            int kq  = (tid >> 5) & 3;
            const __nv_bfloat16* src;
            if (isH) {
                long o = (long)(bm + row) * HID + k0 + kq * 8;
                src = (hi ? hh_in : hl_in) + o;
            } else {
                long o = (long)(bm + row) * (SEQ * IN_DIM) + (long)t * IN_DIM + (k0 - HID) + kq * 8;
                src = (hi ? g_xh : g_xl) + o;
            }
            cp16(st + (hi ? 0 : OFF_AL) + (row * LDW + kq * 8) * 2, src);
        }
        #pragma unroll
        for (int r = 0; r < 2; r++) {   // B: 2 splits x 64 rows x 4 kq = 512 cp16
            int s2  = tid + r * NT;
            int hi  = (s2 < 256);
            int row = s2 & 63;
            int kq  = (s2 >> 6) & 3;
            long o = (long)(bn + row) * KTOT + k0 + kq * 8;
            const __nv_bfloat16* src = (hi ? g_Wh : g_Wl) + o;
            cp16(st + (hi ? OFF_BH : OFF_BL) + (row * LDW + kq * 8) * 2, src);
        }
        cp_commit();
    };

    float ch[2][4] = {}, cm[2][4] = {}, cl[2][4] = {};   // independent chains

    load_chunk(0, 0);
    load_chunk(1, 1);   // NC >= 4 always

    for (int i = 0; i < NC; i++) {
        const int buf = i % NSTAGE;
        if (i + 1 < NC) cp_wait<1>();
        else            cp_wait<0>();
        __syncthreads();                 // fences reuse of stage (i+2)%3 (read in i-1)
        if (i + 2 < NC) load_chunk(i + 2, (i + 2) % NSTAGE);

        const unsigned sb = sbase + (unsigned)(buf * STAGE_B);
        #pragma unroll
        for (int kk = 0; kk < 2; kk++) {             // 2 k16-slices per chunk
            const unsigned o = (unsigned)(kk * 32);  // 16 bf16 = 32B
            unsigned ah[4], al[4], fb[4], fbl[4];
            ldsm4(ah,  sb + aoff + o);
            ldsm4(al,  sb + OFF_AL + aoff + o);
            ldsm4(fb,  sb + OFF_BH + boff + o);
            ldsm4(fbl, sb + OFF_BL + boff + o);
            #pragma unroll
            for (int j = 0; j < 2; j++) {
                mma_bf16(ch[j], ah, fb[2 * j],  fb[2 * j + 1]);    // Ah*Bh
                mma_bf16(cm[j], ah, fbl[2 * j], fbl[2 * j + 1]);   // Ah*Bl
                mma_bf16(cl[j], al, fb[2 * j],  fb[2 * j + 1]);    // Al*Bh
            }
        }
    }

    // epilogue: combine splits, bias + tanh, bf16 hi/lo split, bf162 stores
    #pragma unroll
    for (int j = 0; j < 2; j++) {
        const int col0 = bn + wn * 16 + j * 8 + tg * 2;
        const float b0 = __ldg(&bh[col0]);
        const float b1 = __ldg(&bh[col0 + 1]);
        #pragma unroll
        for (int rh = 0; rh < 2; rh++) {             // row halves g, g+8
            const int row = bm + wm * 16 + g + rh * 8;
            float v0 = (ch[j][rh * 2 + 0] + cm[j][rh * 2 + 0]) + cl[j][rh * 2 + 0];
            float v1 = (ch[j][rh * 2 + 1] + cm[j][rh * 2 + 1]) + cl[j][rh * 2 + 1];
            float h0 = tanhf(v0 + b0);
            float h1 = tanhf(v1 + b1);
            __nv_bfloat16 h0h = __float2bfloat16(h0);
            __nv_bfloat16 h1h = __float2bfloat16(h1);
            __nv_bfloat162 hv, lv;
            hv.x = h0h;
            hv.y = h1h;
            lv.x = __float2bfloat16(h0 - __bfloat162float(h0h));
            lv.y = __float2bfloat16(h1 - __bfloat162float(h1h));
            long o = (long)row * HID + col0;
            *(__nv_bfloat162*)(hh_out + o) = hv;
            *(__nv_bfloat162*)(hl_out + o) = lv;
        }
    }
}

// ---- final projection + softmax ----
__global__ __launch_bounds__(128) void rnn_out(
    const float* __restrict__ Why, const float* __restrict__ bo, float* __restrict__ out)
{
    const int b = blockIdx.x;
    const int tid = threadIdx.x;
    const __nv_bfloat16* hh = g_hh[0];   // t=255 writes buffer 0
    const __nv_bfloat16* hl = g_hl[0];

    float acc[OUT_DIM];
    #pragma unroll
    for (int o = 0; o < OUT_DIM; o++) acc[o] = 0.0f;

    for (int k = tid; k < HID; k += 128) {
        float hv = __bfloat162float(hh[(long)b * HID + k]) +
                   __bfloat162float(hl[(long)b * HID + k]);
        #pragma unroll
        for (int o = 0; o < OUT_DIM; o++)
            acc[o] = fmaf(hv, Why[k * OUT_DIM + o], acc[o]);
    }

    __shared__ float red[128][OUT_DIM];
    #pragma unroll
    for (int o = 0; o < OUT_DIM; o++) red[tid][o] = acc[o];
    __syncthreads();
    for (int s = 64; s > 0; s >>= 1) {
        if (tid < s) {
            #pragma unroll
            for (int o = 0; o < OUT_DIM; o++) red[tid][o] += red[tid + s][o];
        }
        __syncthreads();
    }
    if (tid == 0) {
        float lg[OUT_DIM];
        float mx = -1e30f;
        #pragma unroll
        for (int o = 0; o < OUT_DIM; o++) { lg[o] = red[0][o] + bo[o]; mx = fmaxf(mx, lg[o]); }
        float ssum = 0.0f;
        #pragma unroll
        for (int o = 0; o < OUT_DIM; o++) { lg[o] = expf(lg[o] - mx); ssum += lg[o]; }
        float inv = 1.0f / ssum;
        #pragma unroll
        for (int o = 0; o < OUT_DIM; o++) out[(long)b * OUT_DIM + o] = lg[o] * inv;
    }
}

extern "C" void kernel_launch(void* const* d_in, const int* in_sizes, int n_in,
                              void* d_out, int out_size) {
    const float* x   = (const float*)d_in[0];
    const float* Whx = (const float*)d_in[1];
    const float* Whh = (const float*)d_in[2];
    const float* bh  = (const float*)d_in[3];
    const float* Why = (const float*)d_in[4];
    const float* bo  = (const float*)d_in[5];
    float* out = (float*)d_out;

    cudaFuncSetAttribute(rnn_step, cudaFuncAttributeMaxDynamicSharedMemorySize, DYN_B);

    split_w<<<KTOT, 256>>>(Whh, Whx);
    split_x<<<(BATCH * SEQ * IN_DIM) / 256, 256>>>(x);

    dim3 grid(HID / BN, BATCH / BM);   // (16, 8) = 128 CTAs
    for (int t = 0; t < SEQ; t++)
        rnn_step<<<grid, NT, DYN_B>>>(bh, t);
    rnn_out<<<BATCH, 128>>>(Why, bo, out);
}

// round 12
// speedup vs baseline: 1.8462x; 1.8462x over previous
#include <cuda_runtime.h>
#include <cuda_bf16.h>
#include <cstdint>
#include <math.h>

#define BATCH 256
#define SEQ 256
#define IN_DIM 128
#define HID 1024
#define OUT_DIM 10
#define KTOT 1152            // [h | x_t] fused K
#define BK 128               // big chunks: 9 per step (vs 36) -> 4x fewer sync links
#define BM 32
#define BN 64
#define LDW 136              // bf16 elems per row (272B): +16B/row -> conflict-free ldmatrix
#define NT 256               // 8 warps = 2/SMSP

// stage layout (bytes): Ah[32][136] Al[32][136] Bh[64][136] Bl[64][136]  (bf16)
#define OFF_AL 8704
#define OFF_BH 17408
#define OFF_BL 34816
#define STAGE_B 52224
#define NSTAGE 2
#define DYN_B (NSTAGE * STAGE_B)   // 104448

// ---- device-global scratch (sanctioned) ----
__device__ __nv_bfloat16 g_hh[2][BATCH * HID];   // hidden hi split (ping-pong)
__device__ __nv_bfloat16 g_hl[2][BATCH * HID];   // hidden lo split
__device__ __nv_bfloat16 g_xh[BATCH * SEQ * IN_DIM];
__device__ __nv_bfloat16 g_xl[BATCH * SEQ * IN_DIM];
__device__ __nv_bfloat16 g_Wh[HID * KTOT];       // W^T [n][k] hi
__device__ __nv_bfloat16 g_Wl[HID * KTOT];       // lo

__device__ __forceinline__ void cp16(void* smem_dst, const void* g) {
    unsigned d = (unsigned)__cvta_generic_to_shared(smem_dst);
    asm volatile("cp.async.ca.shared.global [%0], [%1], 16;\n" :: "r"(d), "l"(g));
}
__device__ __forceinline__ void cp_commit() { asm volatile("cp.async.commit_group;\n"); }
template <int N>
__device__ __forceinline__ void cp_wait() { asm volatile("cp.async.wait_group %0;\n" :: "n"(N)); }

__device__ __forceinline__ void ldsm4(unsigned* r, unsigned saddr) {
    asm volatile("ldmatrix.sync.aligned.m8n8.x4.shared.b16 {%0,%1,%2,%3}, [%4];"
                 : "=r"(r[0]), "=r"(r[1]), "=r"(r[2]), "=r"(r[3]) : "r"(saddr));
}
__device__ __forceinline__ void mma_bf16(float* c, const unsigned* a, unsigned b0, unsigned b1) {
    asm volatile(
        "mma.sync.aligned.m16n8k16.row.col.f32.bf16.bf16.f32 "
        "{%0,%1,%2,%3}, {%4,%5,%6,%7}, {%8,%9}, {%0,%1,%2,%3};"
        : "+f"(c[0]), "+f"(c[1]), "+f"(c[2]), "+f"(c[3])
        : "r"(a[0]), "r"(a[1]), "r"(a[2]), "r"(a[3]), "r"(b0), "r"(b1));
}

// ---- prep: transpose + bf16 hi/lo split of W; split x ----
__global__ void split_w(const float* __restrict__ Whh, const float* __restrict__ Whx) {
    int k = blockIdx.x;                          // 0..1151
    for (int n = threadIdx.x; n < HID; n += blockDim.x) {
        float w = (k < HID) ? Whh[(long)k * HID + n] : Whx[(long)(k - HID) * HID + n];
        __nv_bfloat16 hi = __float2bfloat16(w);
        g_Wh[(long)n * KTOT + k] = hi;
        g_Wl[(long)n * KTOT + k] = __float2bfloat16(w - __bfloat162float(hi));
    }
}
__global__ void split_x(const float* __restrict__ x) {
    long i = (long)blockIdx.x * blockDim.x + threadIdx.x;
    if (i < (long)BATCH * SEQ * IN_DIM) {
        float v = x[i];
        __nv_bfloat16 hi = __float2bfloat16(v);
        g_xh[i] = hi;
        g_xl[i] = __float2bfloat16(v - __bfloat162float(hi));
    }
}

// ---- one recurrence step: 3-term bf16 split, BK=128 chunks ----
// grid (16, 8) = 128 CTAs, 256 threads (8 warps), warp tile 16x16 (2m x 4n).
__global__ __launch_bounds__(NT, 1) void rnn_step(
    const float* __restrict__ bh, int t)
{
    extern __shared__ char smem[];

    const int tid  = threadIdx.x;
    const int wid  = tid >> 5;
    const int lane = tid & 31;
    const int g    = lane >> 2;     // fragment group 0..7
    const int tg   = lane & 3;      // thread-in-group 0..3
    const int wm   = wid & 1;       // warp m 0..1 (16 rows)
    const int wn   = wid >> 1;      // warp n 0..3 (16 cols)

    const int bm = blockIdx.y * BM;
    const int bn = blockIdx.x * BN;

    const unsigned sbase = (unsigned)__cvta_generic_to_shared(smem);

    // ldmatrix per-lane source offsets (bytes within a stage), b16 flavor
    const int a_row = wm * 16 + (lane & 15);
    const unsigned aoff = (unsigned)(a_row * LDW + ((lane >> 4) << 3)) * 2u;
    const int b_row = wn * 16 + (lane & 7) + ((lane >> 4) << 3);
    const unsigned boff = (unsigned)(b_row * LDW + (((lane >> 3) & 1) << 3)) * 2u;

    const __nv_bfloat16* hh_in = g_hh[t & 1];
    const __nv_bfloat16* hl_in = g_hl[t & 1];
    __nv_bfloat16* hh_out = g_hh[(t & 1) ^ 1];
    __nv_bfloat16* hl_out = g_hl[(t & 1) ^ 1];

    const int kstart = (t == 0) ? HID : 0;      // t==0: h0==0, only x chunk
    const int NC = (KTOT - kstart) / BK;        // 9 (or 1 at t==0)

    auto load_chunk = [&](int ci, int s) {
        const int k0 = kstart + ci * BK;
        char* st = smem + s * STAGE_B;
        const bool isH = (k0 < HID);
        // A: 2 splits x 32 rows x 16 kq (8 bf16 = 16B) = 1024 cp16
        #pragma unroll
        for (int r = 0; r < 4; r++) {
            int s2  = tid + r * NT;
            int hi  = (s2 < 512);
            int row = (s2 & 511) >> 4;
            int kq  = s2 & 15;
            const __nv_bfloat16* src;
            if (isH) {
                long o = (long)(bm + row) * HID + k0 + kq * 8;
                src = (hi ? hh_in : hl_in) + o;
            } else {
                long o = (long)(bm + row) * (SEQ * IN_DIM) + (long)t * IN_DIM + (k0 - HID) + kq * 8;
                src = (hi ? g_xh : g_xl) + o;
            }
            cp16(st + (hi ? 0 : OFF_AL) + (row * LDW + kq * 8) * 2, src);
        }
        // B: 2 splits x 64 rows x 16 kq = 2048 cp16
        #pragma unroll
        for (int r = 0; r < 8; r++) {
            int s2  = tid + r * NT;
            int hi  = (s2 < 1024);
            int row = (s2 & 1023) >> 4;
            int kq  = s2 & 15;
            long o = (long)(bn + row) * KTOT + k0 + kq * 8;
            const __nv_bfloat16* src = (hi ? g_Wh : g_Wl) + o;
            cp16(st + (hi ? OFF_BH : OFF_BL) + (row * LDW + kq * 8) * 2, src);
        }
        cp_commit();
    };

    float ch[2][4] = {}, cm[2][4] = {}, cl[2][4] = {};   // independent chains

    load_chunk(0, 0);

    for (int i = 0; i < NC; i++) {
        const int buf = i & 1;
        if (i + 1 < NC) {
            load_chunk(i + 1, buf ^ 1);
            cp_wait<1>();
        } else {
            cp_wait<0>();
        }
        __syncthreads();

        const unsigned sb = sbase + (unsigned)(buf * STAGE_B);
        #pragma unroll
        for (int kk = 0; kk < 8; kk++) {             // 8 k16-slices per chunk
            const unsigned o = (unsigned)(kk * 32);  // 16 bf16 = 32B
            unsigned ah[4], al[4], fb[4], fbl[4];
            ldsm4(ah,  sb + aoff + o);
            ldsm4(al,  sb + OFF_AL + aoff + o);
            ldsm4(fb,  sb + OFF_BH + boff + o);
            ldsm4(fbl, sb + OFF_BL + boff + o);
            #pragma unroll
            for (int j = 0; j < 2; j++) {
                mma_bf16(ch[j], ah, fb[2 * j],  fb[2 * j + 1]);    // Ah*Bh
                mma_bf16(cm[j], ah, fbl[2 * j], fbl[2 * j + 1]);   // Ah*Bl
                mma_bf16(cl[j], al, fb[2 * j],  fb[2 * j + 1]);    // Al*Bh
            }
        }
        __syncthreads();     // stage reuse fence (2-stage ring)
    }

    // epilogue: combine splits, bias + tanh, bf16 hi/lo split, bf162 stores
    #pragma unroll
    for (int j = 0; j < 2; j++) {
        const int col0 = bn + wn * 16 + j * 8 + tg * 2;
        const float b0 = __ldg(&bh[col0]);
        const float b1 = __ldg(&bh[col0 + 1]);
        #pragma unroll
        for (int rh = 0; rh < 2; rh++) {             // row halves g, g+8
            const int row = bm + wm * 16 + g + rh * 8;
            float v0 = (ch[j][rh * 2 + 0] + cm[j][rh * 2 + 0]) + cl[j][rh * 2 + 0];
            float v1 = (ch[j][rh * 2 + 1] + cm[j][rh * 2 + 1]) + cl[j][rh * 2 + 1];
            float h0 = tanhf(v0 + b0);
            float h1 = tanhf(v1 + b1);
            __nv_bfloat16 h0h = __float2bfloat16(h0);
            __nv_bfloat16 h1h = __float2bfloat16(h1);
            __nv_bfloat162 hv, lv;
            hv.x = h0h;
            hv.y = h1h;
            lv.x = __float2bfloat16(h0 - __bfloat162float(h0h));
            lv.y = __float2bfloat16(h1 - __bfloat162float(h1h));
            long o = (long)row * HID + col0;
            *(__nv_bfloat162*)(hh_out + o) = hv;
            *(__nv_bfloat162*)(hl_out + o) = lv;
        }
    }
}

// ---- final projection + softmax ----
__global__ __launch_bounds__(128) void rnn_out(
    const float* __restrict__ Why, const float* __restrict__ bo, float* __restrict__ out)
{
    const int b = blockIdx.x;
    const int tid = threadIdx.x;
    const __nv_bfloat16* hh = g_hh[0];   // t=255 writes buffer 0
    const __nv_bfloat16* hl = g_hl[0];

    float acc[OUT_DIM];
    #pragma unroll
    for (int o = 0; o < OUT_DIM; o++) acc[o] = 0.0f;

    for (int k = tid; k < HID; k += 128) {
        float hv = __bfloat162float(hh[(long)b * HID + k]) +
                   __bfloat162float(hl[(long)b * HID + k]);
        #pragma unroll
        for (int o = 0; o < OUT_DIM; o++)
            acc[o] = fmaf(hv, Why[k * OUT_DIM + o], acc[o]);
    }

    __shared__ float red[128][OUT_DIM];
    #pragma unroll
    for (int o = 0; o < OUT_DIM; o++) red[tid][o] = acc[o];
    __syncthreads();
    for (int s = 64; s > 0; s >>= 1) {
        if (tid < s) {
            #pragma unroll
            for (int o = 0; o < OUT_DIM; o++) red[tid][o] += red[tid + s][o];
        }
        __syncthreads();
    }
    if (tid == 0) {
        float lg[OUT_DIM];
        float mx = -1e30f;
        #pragma unroll
        for (int o = 0; o < OUT_DIM; o++) { lg[o] = red[0][o] + bo[o]; mx = fmaxf(mx, lg[o]); }
        float ssum = 0.0f;
        #pragma unroll
        for (int o = 0; o < OUT_DIM; o++) { lg[o] = expf(lg[o] - mx); ssum += lg[o]; }
        float inv = 1.0f / ssum;
        #pragma unroll
        for (int o = 0; o < OUT_DIM; o++) out[(long)b * OUT_DIM + o] = lg[o] * inv;
    }
}

extern "C" void kernel_launch(void* const* d_in, const int* in_sizes, int n_in,
                              void* d_out, int out_size) {
    const float* x   = (const float*)d_in[0];
    const float* Whx = (const float*)d_in[1];
    const float* Whh = (const float*)d_in[2];
    const float* bh  = (const float*)d_in[3];
    const float* Why = (const float*)d_in[4];
    const float* bo  = (const float*)d_in[5];
    float* out = (float*)d_out;

    cudaFuncSetAttribute(rnn_step, cudaFuncAttributeMaxDynamicSharedMemorySize, DYN_B);

    split_w<<<KTOT, 256>>>(Whh, Whx);
    split_x<<<(BATCH * SEQ * IN_DIM) / 256, 256>>>(x);

    dim3 grid(HID / BN, BATCH / BM);   // (16, 8) = 128 CTAs
    for (int t = 0; t < SEQ; t++)
        rnn_step<<<grid, NT, DYN_B>>>(bh, t);
    rnn_out<<<BATCH, 128>>>(Why, bo, out);
}

// round 13
// speedup vs baseline: 2.0562x; 1.1137x over previous
#include <cuda_runtime.h>
#include <cuda_bf16.h>
#include <cstdint>
#include <math.h>

#define BATCH 256
#define SEQ 256
#define IN_DIM 128
#define HID 1024
#define OUT_DIM 10
#define KTOT 1152            // [h | x_t] fused K
#define BK 128               // 9 chunks per step (1 at t=0)
#define BM 64
#define BN 32
#define NT 256               // 8 warps
#define NCTAS 128            // (32 n) x (4 m) — co-resident on 148 SMs
#define LDA 136              // A stage row stride (bf16 elems), 272B = 17x16B
#define LDB 1160             // resident B row stride, 2320B = 145x16B

// smem layout (bytes)
#define OFF_BH 0
#define OFF_BL 74240         // 32*1160*2
#define ABASE  148480
#define A_STAGE 34816        // per stage: 2 splits x 64*136*2
#define A_SPLIT 17408
#define DYN_B  218112        // 148480 + 2*34816

// ---- device-global scratch (sanctioned) ----
__device__ __nv_bfloat16 g_hh[2][BATCH * HID];
__device__ __nv_bfloat16 g_hl[2][BATCH * HID];
__device__ __nv_bfloat16 g_xh[BATCH * SEQ * IN_DIM];
__device__ __nv_bfloat16 g_xl[BATCH * SEQ * IN_DIM];
__device__ __nv_bfloat16 g_Wh[HID * KTOT];       // W^T [n][k] hi
__device__ __nv_bfloat16 g_Wl[HID * KTOT];       // lo
__device__ volatile unsigned g_bar;              // monotonic grid barrier (reset in rnn_out)

__device__ __forceinline__ void cp16cg(void* smem_dst, const void* g) {
    unsigned d = (unsigned)__cvta_generic_to_shared(smem_dst);
    asm volatile("cp.async.cg.shared.global [%0], [%1], 16;\n" :: "r"(d), "l"(g));
}
__device__ __forceinline__ void cp_commit() { asm volatile("cp.async.commit_group;\n"); }
template <int N>
__device__ __forceinline__ void cp_wait() { asm volatile("cp.async.wait_group %0;\n" :: "n"(N)); }

__device__ __forceinline__ void ldsm4(unsigned* r, unsigned saddr) {
    asm volatile("ldmatrix.sync.aligned.m8n8.x4.shared.b16 {%0,%1,%2,%3}, [%4];"
                 : "=r"(r[0]), "=r"(r[1]), "=r"(r[2]), "=r"(r[3]) : "r"(saddr));
}
__device__ __forceinline__ void mma_bf16(float* c, const unsigned* a, unsigned b0, unsigned b1) {
    asm volatile(
        "mma.sync.aligned.m16n8k16.row.col.f32.bf16.bf16.f32 "
        "{%0,%1,%2,%3}, {%4,%5,%6,%7}, {%8,%9}, {%0,%1,%2,%3};"
        : "+f"(c[0]), "+f"(c[1]), "+f"(c[2]), "+f"(c[3])
        : "r"(a[0]), "r"(a[1]), "r"(a[2]), "r"(a[3]), "r"(b0), "r"(b1));
}

// ---- prep: transpose + bf16 hi/lo split of W; split x ----
__global__ void split_w(const float* __restrict__ Whh, const float* __restrict__ Whx) {
    int k = blockIdx.x;                          // 0..1151
    for (int n = threadIdx.x; n < HID; n += blockDim.x) {
        float w = (k < HID) ? Whh[(long)k * HID + n] : Whx[(long)(k - HID) * HID + n];
        __nv_bfloat16 hi = __float2bfloat16(w);
        g_Wh[(long)n * KTOT + k] = hi;
        g_Wl[(long)n * KTOT + k] = __float2bfloat16(w - __bfloat162float(hi));
    }
}
__global__ void split_x(const float* __restrict__ x) {
    long i = (long)blockIdx.x * blockDim.x + threadIdx.x;
    if (i < (long)BATCH * SEQ * IN_DIM) {
        float v = x[i];
        __nv_bfloat16 hi = __float2bfloat16(v);
        g_xh[i] = hi;
        g_xl[i] = __float2bfloat16(v - __bfloat162float(hi));
    }
}

// ---- persistent kernel: all 256 steps; W resident in smem ----
// grid (32, 4) = 128 CTAs, 256 threads; warp tile 16x16 (4m x 2n).
__global__ __launch_bounds__(NT, 1) void rnn_persist(const float* __restrict__ bh)
{
    extern __shared__ char smem[];

    const int tid  = threadIdx.x;
    const int wid  = tid >> 5;
    const int lane = tid & 31;
    const int g    = lane >> 2;
    const int tg   = lane & 3;
    const int wm   = wid & 3;       // warp m 0..3 (16 rows each)
    const int wn   = wid >> 2;      // warp n 0..1 (16 cols each)

    const int bn = blockIdx.x * BN;
    const int bm = blockIdx.y * BM;

    const unsigned sbase = (unsigned)__cvta_generic_to_shared(smem);

    // ldmatrix per-lane offsets
    const int a_row = wm * 16 + (lane & 15);
    const unsigned aoff = (unsigned)(a_row * LDA + ((lane >> 4) << 3)) * 2u;
    const int b_row = wn * 16 + (lane & 7) + ((lane >> 4) << 3);
    const unsigned boff = (unsigned)(b_row * LDB + (((lane >> 3) & 1) << 3)) * 2u;

    // ---- one-time: load resident B slice (rows bn..bn+31, all k, hi+lo) ----
    for (int idx = tid; idx < 32 * 144; idx += NT) {
        int row = idx / 144;
        int kq  = idx % 144;
        long o = (long)(bn + row) * KTOT + kq * 8;
        cp16cg(smem + OFF_BH + (row * LDB + kq * 8) * 2, g_Wh + o);
        cp16cg(smem + OFF_BL + (row * LDB + kq * 8) * 2, g_Wl + o);
    }
    cp_commit();

    for (int t = 0; t < SEQ; t++) {
        const __nv_bfloat16* hh_in = g_hh[t & 1];
        const __nv_bfloat16* hl_in = g_hl[t & 1];
        __nv_bfloat16* hh_out = g_hh[(t & 1) ^ 1];
        __nv_bfloat16* hl_out = g_hl[(t & 1) ^ 1];

        const int c0 = (t == 0) ? 8 : 0;        // t==0: h0==0 -> only x chunk

        auto load_A = [&](int ci, int s) {
            char* st = smem + ABASE + s * A_STAGE;
            const int k0 = ci * BK;
            #pragma unroll
            for (int r = 0; r < 8; r++) {        // 2 splits x 64 rows x 16 kq = 2048 cp16
                int s2  = tid + r * NT;
                int hi  = (s2 < 1024);
                int row = (s2 & 1023) >> 4;
                int kq  = s2 & 15;
                const __nv_bfloat16* src;
                if (ci < 8) {
                    long o = (long)(bm + row) * HID + k0 + kq * 8;
                    src = (hi ? hh_in : hl_in) + o;
                } else {
                    long o = (long)(bm + row) * (SEQ * IN_DIM) + (long)t * IN_DIM + kq * 8;
                    src = (hi ? g_xh : g_xl) + o;
                }
                cp16cg(st + (hi ? 0 : A_SPLIT) + (row * LDA + kq * 8) * 2, src);
            }
            cp_commit();
        };

        float ch[2][4] = {}, cm[2][4] = {}, cl[2][4] = {};

        load_A(c0, 0);

        for (int ci = c0; ci <= 8; ci++) {
            const int s = (ci - c0) & 1;
            if (ci < 8) {
                load_A(ci + 1, s ^ 1);
                cp_wait<1>();
            } else {
                cp_wait<0>();   // also covers resident-B group on first pass
            }
            __syncthreads();

            const unsigned sa = sbase + ABASE + (unsigned)(s * A_STAGE);
            const unsigned kb0 = (unsigned)(ci * BK) * 2u;
            #pragma unroll
            for (int kk = 0; kk < 8; kk++) {
                const unsigned o = (unsigned)(kk * 32);
                unsigned ah[4], al[4], fb[4], fbl[4];
                ldsm4(ah,  sa + aoff + o);
                ldsm4(al,  sa + A_SPLIT + aoff + o);
                ldsm4(fb,  sbase + OFF_BH + boff + kb0 + o);
                ldsm4(fbl, sbase + OFF_BL + boff + kb0 + o);
                #pragma unroll
                for (int j = 0; j < 2; j++) {
                    mma_bf16(ch[j], ah, fb[2 * j],  fb[2 * j + 1]);    // Ah*Bh
                    mma_bf16(cm[j], ah, fbl[2 * j], fbl[2 * j + 1]);   // Ah*Bl
                    mma_bf16(cl[j], al, fb[2 * j],  fb[2 * j + 1]);    // Al*Bh
                }
            }
            __syncthreads();
        }

        // epilogue: bias + tanh, bf16 hi/lo split, store
        #pragma unroll
        for (int j = 0; j < 2; j++) {
            const int col0 = bn + wn * 16 + j * 8 + tg * 2;
            const float b0 = __ldg(&bh[col0]);
            const float b1 = __ldg(&bh[col0 + 1]);
            #pragma unroll
            for (int rh = 0; rh < 2; rh++) {
                const int row = bm + wm * 16 + g + rh * 8;
                float v0 = (ch[j][rh * 2 + 0] + cm[j][rh * 2 + 0]) + cl[j][rh * 2 + 0];
                float v1 = (ch[j][rh * 2 + 1] + cm[j][rh * 2 + 1]) + cl[j][rh * 2 + 1];
                float h0 = tanhf(v0 + b0);
                float h1 = tanhf(v1 + b1);
                __nv_bfloat16 h0h = __float2bfloat16(h0);
                __nv_bfloat16 h1h = __float2bfloat16(h1);
                __nv_bfloat162 hv, lv;
                hv.x = h0h; hv.y = h1h;
                lv.x = __float2bfloat16(h0 - __bfloat162float(h0h));
                lv.y = __float2bfloat16(h1 - __bfloat162float(h1h));
                long o = (long)row * HID + col0;
                *(__nv_bfloat162*)(hh_out + o) = hv;
                *(__nv_bfloat162*)(hl_out + o) = lv;
            }
        }

        // grid barrier (skip after last step); all 128 CTAs co-resident
        if (t + 1 < SEQ) {
            __syncthreads();
            if (tid == 0) {
                __threadfence();
                atomicAdd((unsigned*)&g_bar, 1u);
                const unsigned target = (unsigned)(t + 1) * NCTAS;
                while (g_bar < target) { }
                __threadfence();
            }
            __syncthreads();
        }
    }
}

// ---- final projection + softmax (+ barrier reset for next replay) ----
__global__ __launch_bounds__(128) void rnn_out(
    const float* __restrict__ Why, const float* __restrict__ bo, float* __restrict__ out)
{
    if (blockIdx.x == 0 && threadIdx.x == 0) g_bar = 0u;

    const int b = blockIdx.x;
    const int tid = threadIdx.x;
    const __nv_bfloat16* hh = g_hh[0];   // t=255 writes buffer 0
    const __nv_bfloat16* hl = g_hl[0];

    float acc[OUT_DIM];
    #pragma unroll
    for (int o = 0; o < OUT_DIM; o++) acc[o] = 0.0f;

    for (int k = tid; k < HID; k += 128) {
        float hv = __bfloat162float(hh[(long)b * HID + k]) +
                   __bfloat162float(hl[(long)b * HID + k]);
        #pragma unroll
        for (int o = 0; o < OUT_DIM; o++)
            acc[o] = fmaf(hv, Why[k * OUT_DIM + o], acc[o]);
    }

    __shared__ float red[128][OUT_DIM];
    #pragma unroll
    for (int o = 0; o < OUT_DIM; o++) red[tid][o] = acc[o];
    __syncthreads();
    for (int s = 64; s > 0; s >>= 1) {
        if (tid < s) {
            #pragma unroll
            for (int o = 0; o < OUT_DIM; o++) red[tid][o] += red[tid + s][o];
        }
        __syncthreads();
    }
    if (tid == 0) {
        float lg[OUT_DIM];
        float mx = -1e30f;
        #pragma unroll
        for (int o = 0; o < OUT_DIM; o++) { lg[o] = red[0][o] + bo[o]; mx = fmaxf(mx, lg[o]); }
        float ssum = 0.0f;
        #pragma unroll
        for (int o = 0; o < OUT_DIM; o++) { lg[o] = expf(lg[o] - mx); ssum += lg[o]; }
        float inv = 1.0f / ssum;
        #pragma unroll
        for (int o = 0; o < OUT_DIM; o++) out[(long)b * OUT_DIM + o] = lg[o] * inv;
    }
}

extern "C" void kernel_launch(void* const* d_in, const int* in_sizes, int n_in,
                              void* d_out, int out_size) {
    const float* x   = (const float*)d_in[0];
    const float* Whx = (const float*)d_in[1];
    const float* Whh = (const float*)d_in[2];
    const float* bh  = (const float*)d_in[3];
    const float* Why = (const float*)d_in[4];
    const float* bo  = (const float*)d_in[5];
    float* out = (float*)d_out;

    cudaFuncSetAttribute(rnn_persist, cudaFuncAttributeMaxDynamicSharedMemorySize, DYN_B);

    split_w<<<KTOT, 256>>>(Whh, Whx);
    split_x<<<(BATCH * SEQ * IN_DIM) / 256, 256>>>(x);

    dim3 grid(HID / BN, BATCH / BM);   // (32, 4) = 128 CTAs, co-resident
    rnn_persist<<<grid, NT, DYN_B>>>(bh);
    rnn_out<<<BATCH, 128>>>(Why, bo, out);
}

// round 14
// speedup vs baseline: 2.5729x; 1.2513x over previous
#include <cuda_runtime.h>
#include <cuda_bf16.h>
#include <cstdint>
#include <math.h>

#define BATCH 256
#define SEQ 256
#define IN_DIM 128
#define HID 1024
#define OUT_DIM 10
#define KTOT 1152
#define BK 128
#define BM 64
#define BN 32
#define NT 256
#define LDB 1160             // resident B row stride (bf16), 2320B -> conflict-free ldmatrix

// smem layout (bytes)
#define OFF_BH 0
#define OFF_BL 74240         // 32*1160*2
#define ABASE  148480
#define A_STAGE 32768        // [split][16384]
#define A_SPLIT 16384
#define SLAB 16384
#define DYN_B  214016        // 148480 + 2*32768

// ---- device-global scratch (sanctioned) ----
// blocked, pre-swizzled h: [buf][mb][kc][split][64*128]
__device__ __nv_bfloat16 g_hb[2][4][8][2][8192];
// blocked, pre-swizzled x: [mb][t][split][64*128]
__device__ __nv_bfloat16 g_xb[4][SEQ][2][8192];
__device__ __nv_bfloat16 g_Wh[HID * KTOT];
__device__ __nv_bfloat16 g_Wl[HID * KTOT];
__device__ unsigned g_barm[4];           // per-m-group monotonic barriers

__device__ __forceinline__ void cp16(void* smem_dst, const void* g) {
    unsigned d = (unsigned)__cvta_generic_to_shared(smem_dst);
    asm volatile("cp.async.ca.shared.global [%0], [%1], 16;\n" :: "r"(d), "l"(g));
}
__device__ __forceinline__ void cp_commit() { asm volatile("cp.async.commit_group;\n"); }
template <int N>
__device__ __forceinline__ void cp_wait() { asm volatile("cp.async.wait_group %0;\n" :: "n"(N)); }

__device__ __forceinline__ void mbar_init(unsigned mbar) {
    asm volatile("mbarrier.init.shared.b64 [%0], 1;" :: "r"(mbar) : "memory");
}
__device__ __forceinline__ void mbar_expect(unsigned mbar, unsigned bytes) {
    asm volatile("mbarrier.arrive.expect_tx.shared.b64 _, [%0], %1;"
                 :: "r"(mbar), "r"(bytes) : "memory");
}
__device__ __forceinline__ void bulk_ld(unsigned sdst, const void* gsrc, unsigned bytes, unsigned mbar) {
    asm volatile("cp.async.bulk.shared::cta.global.mbarrier::complete_tx::bytes [%0], [%1], %2, [%3];"
                 :: "r"(sdst), "l"(gsrc), "r"(bytes), "r"(mbar) : "memory");
}
__device__ __forceinline__ void mbar_wait(unsigned mbar, unsigned parity) {
    asm volatile(
        "{\n\t.reg .pred P1;\n\t"
        "WL_%=:\n\t"
        "mbarrier.try_wait.parity.acquire.cta.shared::cta.b64 P1, [%0], %1, 0x989680;\n\t"
        "@P1 bra.uni WD_%=;\n\t"
        "bra.uni WL_%=;\n\t"
        "WD_%=:\n\t}"
        :: "r"(mbar), "r"(parity) : "memory");
}
__device__ __forceinline__ void fence_pa() { asm volatile("fence.proxy.async;" ::: "memory"); }

__device__ __forceinline__ void ldsm4(unsigned* r, unsigned saddr) {
    asm volatile("ldmatrix.sync.aligned.m8n8.x4.shared.b16 {%0,%1,%2,%3}, [%4];"
                 : "=r"(r[0]), "=r"(r[1]), "=r"(r[2]), "=r"(r[3]) : "r"(saddr));
}
__device__ __forceinline__ void mma_bf16(float* c, const unsigned* a, unsigned b0, unsigned b1) {
    asm volatile(
        "mma.sync.aligned.m16n8k16.row.col.f32.bf16.bf16.f32 "
        "{%0,%1,%2,%3}, {%4,%5,%6,%7}, {%8,%9}, {%0,%1,%2,%3};"
        : "+f"(c[0]), "+f"(c[1]), "+f"(c[2]), "+f"(c[3])
        : "r"(a[0]), "r"(a[1]), "r"(a[2]), "r"(a[3]), "r"(b0), "r"(b1));
}

// ---- prep ----
__global__ void split_w(const float* __restrict__ Whh, const float* __restrict__ Whx) {
    int k = blockIdx.x;
    for (int n = threadIdx.x; n < HID; n += blockDim.x) {
        float w = (k < HID) ? Whh[(long)k * HID + n] : Whx[(long)(k - HID) * HID + n];
        __nv_bfloat16 hi = __float2bfloat16(w);
        g_Wh[(long)n * KTOT + k] = hi;
        g_Wl[(long)n * KTOT + k] = __float2bfloat16(w - __bfloat162float(hi));
    }
}
__global__ void split_x(const float* __restrict__ x) {
    long idx = (long)blockIdx.x * blockDim.x + threadIdx.x;
    if (idx >= (long)BATCH * SEQ * IN_DIM) return;
    int b = (int)(idx / (SEQ * IN_DIM));
    int rem = (int)(idx % (SEQ * IN_DIM));
    int s = rem / IN_DIM;
    int i = rem % IN_DIM;
    float v = x[idx];
    __nv_bfloat16 hi = __float2bfloat16(v);
    __nv_bfloat16 lo = __float2bfloat16(v - __bfloat162float(hi));
    int mb = b >> 6, r = b & 63;
    unsigned byte = (unsigned)(r * 128 + i) * 2u;
    unsigned swb = byte ^ (((unsigned)(r & 7)) << 4);
    char* slab = (char*)&g_xb[mb][s][0][0];
    *(__nv_bfloat16*)(slab + swb) = hi;
    *(__nv_bfloat16*)(slab + SLAB + swb) = lo;
}

// ---- persistent kernel ----
// grid (32, 4) = 128 CTAs, 256 threads; warp tile 16x16 (4m x 2n).
__global__ __launch_bounds__(NT, 1) void rnn_persist(const float* __restrict__ bh)
{
    extern __shared__ char smem[];
    __shared__ __align__(8) unsigned long long mbars[2];

    const int tid  = threadIdx.x;
    const int wid  = tid >> 5;
    const int lane = tid & 31;
    const int g    = lane >> 2;
    const int tg   = lane & 3;
    const int wm   = wid & 3;
    const int wn   = wid >> 2;

    const int mb = blockIdx.y;                  // m-group 0..3
    const int bn = blockIdx.x * BN;

    const unsigned sbase = (unsigned)__cvta_generic_to_shared(smem);
    const unsigned mb0 = (unsigned)__cvta_generic_to_shared(&mbars[0]);
    const unsigned mb1 = (unsigned)__cvta_generic_to_shared(&mbars[1]);

    // A ldmatrix per-lane pieces (swizzled linear slab: row*256B, XOR (r&7)<<4)
    const int r = wm * 16 + (lane & 15);        // 0..63
    const unsigned rbase = (unsigned)r * 256u;
    const unsigned rx = (unsigned)(r & 7);
    const unsigned b16a = (lane >> 4) & 1;
    // B ldmatrix offsets (resident W, LDB stride)
    const int b_row = wn * 16 + (lane & 7) + ((lane >> 4) << 3);
    const unsigned boff = (unsigned)(b_row * LDB + (((lane >> 3) & 1) << 3)) * 2u;

    // one-time: resident B slice + mbar init
    if (tid == 0) { mbar_init(mb0); mbar_init(mb1); fence_pa(); }
    for (int idx = tid; idx < 32 * 144; idx += NT) {
        int row = idx / 144;
        int kq  = idx % 144;
        long o = (long)(bn + row) * KTOT + kq * 8;
        cp16(smem + OFF_BH + (row * LDB + kq * 8) * 2, g_Wh + o);
        cp16(smem + OFF_BL + (row * LDB + kq * 8) * 2, g_Wl + o);
    }
    cp_commit();
    cp_wait<0>();
    __syncthreads();

    unsigned ph[2] = {0u, 0u};

    for (int t = 0; t < SEQ; t++) {
        const int hin = t & 1, hout = hin ^ 1;
        const int c0 = (t == 0) ? 8 : 0;

        auto slab_src = [&](int ci, int split) -> const void* {
            if (ci < 8) return (const void*)&g_hb[hin][mb][ci][split][0];
            return (const void*)&g_xb[mb][t][split][0];
        };

        if (tid == 0) {
            mbar_expect(mb0, 2 * SLAB);
            bulk_ld(sbase + ABASE, slab_src(c0, 0), SLAB, mb0);
            bulk_ld(sbase + ABASE + A_SPLIT, slab_src(c0, 1), SLAB, mb0);
        }

        float ch[2][4] = {}, cm[2][4] = {}, cl[2][4] = {};

        for (int ci = c0; ci <= 8; ci++) {
            const int s = (ci - c0) & 1;
            mbar_wait(s ? mb1 : mb0, ph[s] & 1u);
            ph[s]++;
            __syncthreads();   // all warps done reading stage s^1 (iter ci-1)

            if (ci < 8 && tid == 0) {
                const unsigned d = sbase + ABASE + (unsigned)((s ^ 1) * A_STAGE);
                mbar_expect(s ? mb0 : mb1, 2 * SLAB);
                bulk_ld(d, slab_src(ci + 1, 0), SLAB, s ? mb0 : mb1);
                bulk_ld(d + A_SPLIT, slab_src(ci + 1, 1), SLAB, s ? mb0 : mb1);
            }

            const unsigned sa = sbase + ABASE + (unsigned)(s * A_STAGE);
            const unsigned kb0 = (unsigned)(ci * BK) * 2u;
            #pragma unroll
            for (int kk = 0; kk < 8; kk++) {
                const unsigned col16 = (unsigned)(kk * 2) + b16a;
                const unsigned ao = rbase + ((col16 ^ rx) << 4);
                const unsigned o = (unsigned)(kk * 32);
                unsigned ah[4], al[4], fb[4], fbl[4];
                ldsm4(ah,  sa + ao);
                ldsm4(al,  sa + A_SPLIT + ao);
                ldsm4(fb,  sbase + OFF_BH + boff + kb0 + o);
                ldsm4(fbl, sbase + OFF_BL + boff + kb0 + o);
                #pragma unroll
                for (int j = 0; j < 2; j++) {
                    mma_bf16(ch[j], ah, fb[2 * j],  fb[2 * j + 1]);
                    mma_bf16(cm[j], ah, fbl[2 * j], fbl[2 * j + 1]);
                    mma_bf16(cl[j], al, fb[2 * j],  fb[2 * j + 1]);
                }
            }
        }

        // epilogue: bias + tanh, bf16 hi/lo split, write blocked+swizzled h
        #pragma unroll
        for (int j = 0; j < 2; j++) {
            const int col = bn + wn * 16 + j * 8 + tg * 2;
            const int kc = col >> 7, cc = col & 127;
            const float b0 = __ldg(&bh[col]);
            const float b1 = __ldg(&bh[col + 1]);
            char* slabH = (char*)&g_hb[hout][mb][kc][0][0];
            #pragma unroll
            for (int rh = 0; rh < 2; rh++) {
                const int rl = wm * 16 + g + rh * 8;     // local row 0..63
                float v0 = (ch[j][rh * 2 + 0] + cm[j][rh * 2 + 0]) + cl[j][rh * 2 + 0];
                float v1 = (ch[j][rh * 2 + 1] + cm[j][rh * 2 + 1]) + cl[j][rh * 2 + 1];
                float h0 = tanhf(v0 + b0);
                float h1 = tanhf(v1 + b1);
                __nv_bfloat16 h0h = __float2bfloat16(h0);
                __nv_bfloat16 h1h = __float2bfloat16(h1);
                __nv_bfloat162 hv, lv;
                hv.x = h0h; hv.y = h1h;
                lv.x = __float2bfloat16(h0 - __bfloat162float(h0h));
                lv.y = __float2bfloat16(h1 - __bfloat162float(h1h));
                unsigned byte = (unsigned)(rl * 128 + cc) * 2u;
                unsigned swb = byte ^ (((unsigned)(rl & 7)) << 4);
                *(__nv_bfloat162*)(slabH + swb) = hv;
                *(__nv_bfloat162*)(slabH + SLAB + swb) = lv;
            }
        }

        // per-m-group barrier (32 CTAs each) — h rows only couple same-mb CTAs
        if (t + 1 < SEQ) {
            __syncthreads();
            if (tid == 0) {
                __threadfence();
                fence_pa();
                atomicAdd(&g_barm[mb], 1u);
                const unsigned target = (unsigned)(t + 1) * 32u;
                while (*(volatile unsigned*)&g_barm[mb] < target) { }
                __threadfence();
            }
            __syncthreads();
        }
    }
}

// ---- final projection + softmax (+ barrier reset for next replay) ----
__global__ __launch_bounds__(128) void rnn_out(
    const float* __restrict__ Why, const float* __restrict__ bo, float* __restrict__ out)
{
    if (blockIdx.x == 0 && threadIdx.x < 4) g_barm[threadIdx.x] = 0u;

    const int b = blockIdx.x;
    const int tid = threadIdx.x;
    const int mb = b >> 6, r = b & 63;

    float acc[OUT_DIM];
    #pragma unroll
    for (int o = 0; o < OUT_DIM; o++) acc[o] = 0.0f;

    for (int k = tid; k < HID; k += 128) {
        int kc = k >> 7, cc = k & 127;
        unsigned byte = ((unsigned)(r * 128 + cc) * 2u) ^ (((unsigned)(r & 7)) << 4);
        const char* slab = (const char*)&g_hb[0][mb][kc][0][0];   // t=255 -> buffer 0
        float hv = __bfloat162float(*(const __nv_bfloat16*)(slab + byte)) +
                   __bfloat162float(*(const __nv_bfloat16*)(slab + SLAB + byte));
        #pragma unroll
        for (int o = 0; o < OUT_DIM; o++)
            acc[o] = fmaf(hv, Why[k * OUT_DIM + o], acc[o]);
    }

    __shared__ float red[128][OUT_DIM];
    #pragma unroll
    for (int o = 0; o < OUT_DIM; o++) red[tid][o] = acc[o];
    __syncthreads();
    for (int s = 64; s > 0; s >>= 1) {
        if (tid < s) {
            #pragma unroll
            for (int o = 0; o < OUT_DIM; o++) red[tid][o] += red[tid + s][o];
        }
        __syncthreads();
    }
    if (tid == 0) {
        float lg[OUT_DIM];
        float mx = -1e30f;
        #pragma unroll
        for (int o = 0; o < OUT_DIM; o++) { lg[o] = red[0][o] + bo[o]; mx = fmaxf(mx, lg[o]); }
        float ssum = 0.0f;
        #pragma unroll
        for (int o = 0; o < OUT_DIM; o++) { lg[o] = expf(lg[o] - mx); ssum += lg[o]; }
        float inv = 1.0f / ssum;
        #pragma unroll
        for (int o = 0; o < OUT_DIM; o++) out[(long)b * OUT_DIM + o] = lg[o] * inv;
    }
}

extern "C" void kernel_launch(void* const* d_in, const int* in_sizes, int n_in,
                              void* d_out, int out_size) {
    const float* x   = (const float*)d_in[0];
    const float* Whx = (const float*)d_in[1];
    const float* Whh = (const float*)d_in[2];
    const float* bh  = (const float*)d_in[3];
    const float* Why = (const float*)d_in[4];
    const float* bo  = (const float*)d_in[5];
    float* out = (float*)d_out;

    cudaFuncSetAttribute(rnn_persist, cudaFuncAttributeMaxDynamicSharedMemorySize, DYN_B);

    split_w<<<KTOT, 256>>>(Whh, Whx);
    split_x<<<(BATCH * SEQ * IN_DIM + 255) / 256, 256>>>(x);

    dim3 grid(HID / BN, BATCH / BM);   // (32, 4) = 128 CTAs, co-resident
    rnn_persist<<<grid, NT, DYN_B>>>(bh);
    rnn_out<<<BATCH, 128>>>(Why, bo, out);
}

// round 15
// speedup vs baseline: 2.6836x; 1.0430x over previous
#include <cuda_runtime.h>
#include <cuda_bf16.h>
#include <cstdint>
#include <math.h>

#define BATCH 256
#define SEQ 256
#define IN_DIM 128
#define HID 1024
#define OUT_DIM 10
#define KTOT 1152
#define BK 128
#define BM 64
#define BN 32
#define NT 256
#define SLAB 16384           // A split slab (64 rows x 256B)
#define WSLAB 8192           // W split slab (32 rows x 256B)

// smem layout (bytes)
#define WH_RES 73728         // 9 chunks x 8192, resident Wh
#define STG0 73728
#define STG_STRIDE 40960     // [Ah 16384][Al 16384][Wl 8192]
#define DYN_B 196608         // 73728 + 3*40960

// ---- device-global scratch (sanctioned) ----
__device__ __align__(16) __nv_bfloat16 g_hb[2][4][8][2][8192];   // [buf][mb][kc][split] swizzled
__device__ __align__(16) __nv_bfloat16 g_xb[4][SEQ][2][8192];    // [mb][t][split] swizzled
__device__ __align__(16) __nv_bfloat16 g_Whb[32][9][4096];       // [ng][ci] swizzled 8KB slabs
__device__ __align__(16) __nv_bfloat16 g_Wlb[32][9][4096];
__device__ unsigned g_barm[4];           // per-m-group monotonic barriers

__device__ __forceinline__ void cp16(void* smem_dst, const void* g) {
    unsigned d = (unsigned)__cvta_generic_to_shared(smem_dst);
    asm volatile("cp.async.ca.shared.global [%0], [%1], 16;\n" :: "r"(d), "l"(g));
}
__device__ __forceinline__ void cp_commit() { asm volatile("cp.async.commit_group;\n"); }
template <int N>
__device__ __forceinline__ void cp_wait() { asm volatile("cp.async.wait_group %0;\n" :: "n"(N)); }

__device__ __forceinline__ void mbar_init(unsigned mbar) {
    asm volatile("mbarrier.init.shared.b64 [%0], 1;" :: "r"(mbar) : "memory");
}
__device__ __forceinline__ void mbar_expect(unsigned mbar, unsigned bytes) {
    asm volatile("mbarrier.arrive.expect_tx.shared.b64 _, [%0], %1;"
                 :: "r"(mbar), "r"(bytes) : "memory");
}
__device__ __forceinline__ void bulk_ld(unsigned sdst, const void* gsrc, unsigned bytes, unsigned mbar) {
    asm volatile("cp.async.bulk.shared::cta.global.mbarrier::complete_tx::bytes [%0], [%1], %2, [%3];"
                 :: "r"(sdst), "l"(gsrc), "r"(bytes), "r"(mbar) : "memory");
}
__device__ __forceinline__ void mbar_wait(unsigned mbar, unsigned parity) {
    asm volatile(
        "{\n\t.reg .pred P1;\n\t"
        "WL_%=:\n\t"
        "mbarrier.try_wait.parity.acquire.cta.shared::cta.b64 P1, [%0], %1, 0x989680;\n\t"
        "@P1 bra.uni WD_%=;\n\t"
        "bra.uni WL_%=;\n\t"
        "WD_%=:\n\t}"
        :: "r"(mbar), "r"(parity) : "memory");
}
__device__ __forceinline__ void fence_pa() { asm volatile("fence.proxy.async;" ::: "memory"); }

__device__ __forceinline__ void ldsm4(unsigned* r, unsigned saddr) {
    asm volatile("ldmatrix.sync.aligned.m8n8.x4.shared.b16 {%0,%1,%2,%3}, [%4];"
                 : "=r"(r[0]), "=r"(r[1]), "=r"(r[2]), "=r"(r[3]) : "r"(saddr));
}
__device__ __forceinline__ void mma_bf16(float* c, const unsigned* a, unsigned b0, unsigned b1) {
    asm volatile(
        "mma.sync.aligned.m16n8k16.row.col.f32.bf16.bf16.f32 "
        "{%0,%1,%2,%3}, {%4,%5,%6,%7}, {%8,%9}, {%0,%1,%2,%3};"
        : "+f"(c[0]), "+f"(c[1]), "+f"(c[2]), "+f"(c[3])
        : "r"(a[0]), "r"(a[1]), "r"(a[2]), "r"(a[3]), "r"(b0), "r"(b1));
}

// ---- prep: W -> transposed, split, blocked+swizzled slabs ----
__global__ void split_w(const float* __restrict__ Whh, const float* __restrict__ Whx) {
    int k = blockIdx.x;                          // 0..1151
    const int ci = k >> 7, kc = k & 127;
    const int col16 = kc >> 3, b2 = (kc & 7) * 2;
    for (int n = threadIdx.x; n < HID; n += blockDim.x) {
        float w = (k < HID) ? Whh[(long)k * HID + n] : Whx[(long)(k - HID) * HID + n];
        __nv_bfloat16 hi = __float2bfloat16(w);
        __nv_bfloat16 lo = __float2bfloat16(w - __bfloat162float(hi));
        int ng = n >> 5, row = n & 31;
        unsigned byte = (unsigned)(row * 256) + (((unsigned)col16 ^ (unsigned)(row & 7)) << 4) + b2;
        *(__nv_bfloat16*)((char*)&g_Whb[ng][ci][0] + byte) = hi;
        *(__nv_bfloat16*)((char*)&g_Wlb[ng][ci][0] + byte) = lo;
    }
}
__global__ void split_x(const float* __restrict__ x) {
    long idx = (long)blockIdx.x * blockDim.x + threadIdx.x;
    if (idx >= (long)BATCH * SEQ * IN_DIM) return;
    int b = (int)(idx / (SEQ * IN_DIM));
    int rem = (int)(idx % (SEQ * IN_DIM));
    int s = rem / IN_DIM;
    int i = rem % IN_DIM;
    float v = x[idx];
    __nv_bfloat16 hi = __float2bfloat16(v);
    __nv_bfloat16 lo = __float2bfloat16(v - __bfloat162float(hi));
    int mb = b >> 6, r = b & 63;
    unsigned byte = (unsigned)(r * 128 + i) * 2u;
    unsigned swb = byte ^ (((unsigned)(r & 7)) << 4);
    char* slab = (char*)&g_xb[mb][s][0][0];
    *(__nv_bfloat16*)(slab + swb) = hi;
    *(__nv_bfloat16*)(slab + SLAB + swb) = lo;
}

// ---- persistent kernel: Wh resident; A + Wl bulk-streamed, 3-stage ring ----
// grid (32, 4) = 128 CTAs, 256 threads; warp tile 16x16 (4m x 2n).
__global__ __launch_bounds__(NT, 1) void rnn_persist(const float* __restrict__ bh)
{
    extern __shared__ char smem[];
    __shared__ __align__(8) unsigned long long mbars[3];

    const int tid  = threadIdx.x;
    const int wid  = tid >> 5;
    const int lane = tid & 31;
    const int g    = lane >> 2;
    const int tg   = lane & 3;
    const int wm   = wid & 3;
    const int wn   = wid >> 2;

    const int ng = blockIdx.x;                  // n-group 0..31
    const int mb = blockIdx.y;                  // m-group 0..3
    const int bn = ng * BN;

    const unsigned sbase = (unsigned)__cvta_generic_to_shared(smem);
    unsigned mbarr[3];
    #pragma unroll
    for (int i = 0; i < 3; i++) mbarr[i] = (unsigned)__cvta_generic_to_shared(&mbars[i]);

    // A-frag per-lane pieces (64-row slab, 256B rows, XOR (r&7) on col16)
    const int ar = wm * 16 + (lane & 15);
    const unsigned arbase = (unsigned)ar * 256u;
    const unsigned arx = (unsigned)(ar & 7);
    const unsigned asel = (lane >> 4) & 1;
    // B-frag per-lane pieces (32-row slab, 256B rows)
    const int br = wn * 16 + (lane & 7) + ((lane >> 4) << 3);
    const unsigned brbase = (unsigned)br * 256u;
    const unsigned brx = (unsigned)(br & 7);
    const unsigned bsel = (lane >> 3) & 1;

    // one-time: init mbars, load resident Wh (9 slabs, contiguous per ng)
    if (tid == 0) {
        #pragma unroll
        for (int i = 0; i < 3; i++) mbar_init(mbarr[i]);
        fence_pa();
    }
    {
        const char* src = (const char*)&g_Whb[ng][0][0];
        for (int i = tid; i < WH_RES / 16; i += NT)
            cp16(smem + i * 16, src + i * 16);
    }
    cp_commit();
    cp_wait<0>();
    __syncthreads();

    unsigned ph[3] = {0u, 0u, 0u};

    for (int t = 0; t < SEQ; t++) {
        const int hin = t & 1, hout = hin ^ 1;
        const int c0 = (t == 0) ? 8 : 0;

        auto issue = [&](int ci, int s) {
            const unsigned st = sbase + STG0 + (unsigned)(s * STG_STRIDE);
            const char* ah;
            const char* al;
            if (ci < 8) {
                ah = (const char*)&g_hb[hin][mb][ci][0][0];
                al = (const char*)&g_hb[hin][mb][ci][1][0];
            } else {
                ah = (const char*)&g_xb[mb][t][0][0];
                al = (const char*)&g_xb[mb][t][1][0];
            }
            mbar_expect(mbarr[s], 2 * SLAB + WSLAB);
            bulk_ld(st, ah, SLAB, mbarr[s]);
            bulk_ld(st + SLAB, al, SLAB, mbarr[s]);
            bulk_ld(st + 2 * SLAB, (const char*)&g_Wlb[ng][ci][0], WSLAB, mbarr[s]);
        };

        if (tid == 0) {
            issue(c0, 0);
            if (c0 + 1 <= 8) issue(c0 + 1, 1);
        }

        float ch[2][4] = {}, cm[2][4] = {}, cl[2][4] = {};

        for (int ci = c0; ci <= 8; ci++) {
            const int s = (ci - c0) % 3;
            mbar_wait(mbarr[s], ph[s] & 1u);
            ph[s]++;
            __syncthreads();   // all warps done reading stage (s+2)%3 (iter ci-1)

            if (ci + 2 <= 8 && tid == 0) issue(ci + 2, (ci - c0 + 2) % 3);

            const unsigned sa = sbase + STG0 + (unsigned)(s * STG_STRIDE);
            const unsigned wh = sbase + (unsigned)(ci * WSLAB);
            #pragma unroll
            for (int kk = 0; kk < 8; kk++) {
                const unsigned ca = (unsigned)(kk * 2) + asel;
                const unsigned ao = arbase + ((ca ^ arx) << 4);
                const unsigned cb = (unsigned)(kk * 2) + bsel;
                const unsigned bo = brbase + ((cb ^ brx) << 4);
                unsigned ah[4], al[4], fb[4], fbl[4];
                ldsm4(ah,  sa + ao);
                ldsm4(al,  sa + SLAB + ao);
                ldsm4(fb,  wh + bo);
                ldsm4(fbl, sa + 2 * SLAB + bo);
                #pragma unroll
                for (int j = 0; j < 2; j++) {
                    mma_bf16(ch[j], ah, fb[2 * j],  fb[2 * j + 1]);
                    mma_bf16(cm[j], ah, fbl[2 * j], fbl[2 * j + 1]);
                    mma_bf16(cl[j], al, fb[2 * j],  fb[2 * j + 1]);
                }
            }
        }

        // epilogue: bias + tanh, bf16 hi/lo split, write blocked+swizzled h
        #pragma unroll
        for (int j = 0; j < 2; j++) {
            const int col = bn + wn * 16 + j * 8 + tg * 2;
            const int kc = col >> 7, cc = col & 127;
            const float b0 = __ldg(&bh[col]);
            const float b1 = __ldg(&bh[col + 1]);
            char* slabH = (char*)&g_hb[hout][mb][kc][0][0];
            #pragma unroll
            for (int rh = 0; rh < 2; rh++) {
                const int rl = wm * 16 + g + rh * 8;
                float v0 = (ch[j][rh * 2 + 0] + cm[j][rh * 2 + 0]) + cl[j][rh * 2 + 0];
                float v1 = (ch[j][rh * 2 + 1] + cm[j][rh * 2 + 1]) + cl[j][rh * 2 + 1];
                float h0 = tanhf(v0 + b0);
                float h1 = tanhf(v1 + b1);
                __nv_bfloat16 h0h = __float2bfloat16(h0);
                __nv_bfloat16 h1h = __float2bfloat16(h1);
                __nv_bfloat162 hv, lv;
                hv.x = h0h; hv.y = h1h;
                lv.x = __float2bfloat16(h0 - __bfloat162float(h0h));
                lv.y = __float2bfloat16(h1 - __bfloat162float(h1h));
                unsigned byte = (unsigned)(rl * 128 + cc) * 2u;
                unsigned swb = byte ^ (((unsigned)(rl & 7)) << 4);
                *(__nv_bfloat162*)(slabH + swb) = hv;
                *(__nv_bfloat162*)(slabH + SLAB + swb) = lv;
            }
        }

        // per-m-group barrier (32 CTAs each)
        if (t + 1 < SEQ) {
            __syncthreads();
            if (tid == 0) {
                __threadfence();
                atomicAdd(&g_barm[mb], 1u);
                const unsigned target = (unsigned)(t + 1) * 32u;
                while (*(volatile unsigned*)&g_barm[mb] < target) { }
                __threadfence();
            }
            __syncthreads();
        }
    }
}

// ---- final projection + softmax (+ barrier reset for next replay) ----
__global__ __launch_bounds__(128) void rnn_out(
    const float* __restrict__ Why, const float* __restrict__ bo, float* __restrict__ out)
{
    if (blockIdx.x == 0 && threadIdx.x < 4) g_barm[threadIdx.x] = 0u;

    const int b = blockIdx.x;
    const int tid = threadIdx.x;
    const int mb = b >> 6, r = b & 63;

    float acc[OUT_DIM];
    #pragma unroll
    for (int o = 0; o < OUT_DIM; o++) acc[o] = 0.0f;

    for (int k = tid; k < HID; k += 128) {
        int kc = k >> 7, cc = k & 127;
        unsigned byte = ((unsigned)(r * 128 + cc) * 2u) ^ (((unsigned)(r & 7)) << 4);
        const char* slab = (const char*)&g_hb[0][mb][kc][0][0];   // t=255 -> buffer 0
        float hv = __bfloat162float(*(const __nv_bfloat16*)(slab + byte)) +
                   __bfloat162float(*(const __nv_bfloat16*)(slab + SLAB + byte));
        #pragma unroll
        for (int o = 0; o < OUT_DIM; o++)
            acc[o] = fmaf(hv, Why[k * OUT_DIM + o], acc[o]);
    }

    __shared__ float red[128][OUT_DIM];
    #pragma unroll
    for (int o = 0; o < OUT_DIM; o++) red[tid][o] = acc[o];
    __syncthreads();
    for (int s = 64; s > 0; s >>= 1) {
        if (tid < s) {
            #pragma unroll
            for (int o = 0; o < OUT_DIM; o++) red[tid][o] += red[tid + s][o];
        }
        __syncthreads();
    }
    if (tid == 0) {
        float lg[OUT_DIM];
        float mx = -1e30f;
        #pragma unroll
        for (int o = 0; o < OUT_DIM; o++) { lg[o] = red[0][o] + bo[o]; mx = fmaxf(mx, lg[o]); }
        float ssum = 0.0f;
        #pragma unroll
        for (int o = 0; o < OUT_DIM; o++) { lg[o] = expf(lg[o] - mx); ssum += lg[o]; }
        float inv = 1.0f / ssum;
        #pragma unroll
        for (int o = 0; o < OUT_DIM; o++) out[(long)b * OUT_DIM + o] = lg[o] * inv;
    }
}

extern "C" void kernel_launch(void* const* d_in, const int* in_sizes, int n_in,
                              void* d_out, int out_size) {
    const float* x   = (const float*)d_in[0];
    const float* Whx = (const float*)d_in[1];
    const float* Whh = (const float*)d_in[2];
    const float* bh  = (const float*)d_in[3];
    const float* Why = (const float*)d_in[4];
    const float* bo  = (const float*)d_in[5];
    float* out = (float*)d_out;

    cudaFuncSetAttribute(rnn_persist, cudaFuncAttributeMaxDynamicSharedMemorySize, DYN_B);

    split_w<<<KTOT, 256>>>(Whh, Whx);
    split_x<<<(BATCH * SEQ * IN_DIM + 255) / 256, 256>>>(x);

    dim3 grid(HID / BN, BATCH / BM);   // (32, 4) = 128 CTAs, co-resident
    rnn_persist<<<grid, NT, DYN_B>>>(bh);
    rnn_out<<<BATCH, 128>>>(Why, bo, out);
}